// round 13
// baseline (speedup 1.0000x reference)
#include <cuda_runtime.h>
#include <cuda_bf16.h>
#include <cstdint>
#include <cstddef>

// ============================================================================
// BitLinear on GB300, sm_103 baseline-PTX path:
//   bf16 HMMA GEMM on integer codes:  y = (absmax-int8(x)) @ ternary(W)^T + b
// codes exact in bf16; fp32 accum exact (|sum| < 2^24).
// R13: GEMM frozen (R11). k_quant: 16B stores + __ldcs streaming loads,
//      lane owns 64 consecutive floats. k_ternarize: 8 elems/thread.
// ============================================================================

static constexpr int D_IN  = 2048;
static constexpr int D_OUT = 2048;
static constexpr int M_TOT = 32768;   // 4 * 8192

// scratch (allocation-free rule: device globals)
__device__ __nv_bfloat16 g_qx[(size_t)M_TOT * D_IN];   // 128 MB activation codes
__device__ __nv_bfloat16 g_wq[(size_t)D_OUT * D_IN];   // 8 MB ternary codes
__device__ float  g_scales[M_TOT];                     // per-row activation scale
__device__ float  g_partial[2048];                     // |W| partial sums
__device__ float  g_alpha;                             // ternary scale
__device__ unsigned int g_ctr;                         // last-block counter (self-resetting)

// ---------------------------------------------------------------------------
__device__ __forceinline__ float qclip(float v, float s, float lo, float hi) {
    return fminf(fmaxf(rintf(__fdiv_rn(v, s)), lo), hi);
}

__device__ __forceinline__ uint32_t smem_u32(const void* p) {
    uint32_t a;
    asm("{ .reg .u64 t; cvta.to.shared.u64 t, %1; cvt.u32.u64 %0, t; }"
        : "=r"(a) : "l"(p));
    return a;
}

#define LDSM_X4(r, addr) \
    asm volatile("ldmatrix.sync.aligned.m8n8.x4.shared.b16 {%0,%1,%2,%3}, [%4];" \
        : "=r"((r)[0]), "=r"((r)[1]), "=r"((r)[2]), "=r"((r)[3]) : "r"(addr))

// ---------------------------------------------------------------------------
// Kernel 1 (fused): per-block |W| partial sums + last-block final reduce.
// ---------------------------------------------------------------------------
__global__ void k_walpha(const float* __restrict__ w) {
    __shared__ float sh[256];
    __shared__ bool last;
    const int t = threadIdx.x;
    const float4* p = reinterpret_cast<const float4*>(w + (size_t)blockIdx.x * 2048);
    float s = 0.0f;
#pragma unroll
    for (int k = 0; k < 2; ++k) {
        float4 v = p[2 * t + k];
        s += fabsf(v.x) + fabsf(v.y) + fabsf(v.z) + fabsf(v.w);
    }
    sh[t] = s; __syncthreads();
    for (int o = 128; o > 0; o >>= 1) {
        if (t < o) sh[t] += sh[t + o];
        __syncthreads();
    }
    if (t == 0) {
        g_partial[blockIdx.x] = sh[0];
        __threadfence();
        last = (atomicAdd(&g_ctr, 1u) == 2047u);
    }
    __syncthreads();
    if (last) {
        float f = 0.0f;
        for (int i = t; i < 2048; i += 256) f += g_partial[i];
        sh[t] = f; __syncthreads();
        for (int o = 128; o > 0; o >>= 1) {
            if (t < o) sh[t] += sh[t + o];
            __syncthreads();
        }
        if (t == 0) {
            g_alpha = fmaxf(sh[0] * (1.0f / 4194304.0f), 1e-5f);
            g_ctr = 0u;          // reset for next graph replay
        }
    }
}

// Kernel 2: ternarize W -> bf16 codes {-1,0,1}; 8 elems/thread
__global__ void k_ternarize(const float* __restrict__ w) {
    const size_t i = ((size_t)blockIdx.x * 256 + threadIdx.x) * 8;
    const float a = g_alpha;
    float4 v0 = __ldcs(reinterpret_cast<const float4*>(w + i));
    float4 v1 = __ldcs(reinterpret_cast<const float4*>(w + i + 4));
    union { uint4 u; __nv_bfloat16 h[8]; } pk;
    pk.h[0] = __float2bfloat16_rn(qclip(v0.x, a, -1.0f, 1.0f));
    pk.h[1] = __float2bfloat16_rn(qclip(v0.y, a, -1.0f, 1.0f));
    pk.h[2] = __float2bfloat16_rn(qclip(v0.z, a, -1.0f, 1.0f));
    pk.h[3] = __float2bfloat16_rn(qclip(v0.w, a, -1.0f, 1.0f));
    pk.h[4] = __float2bfloat16_rn(qclip(v1.x, a, -1.0f, 1.0f));
    pk.h[5] = __float2bfloat16_rn(qclip(v1.y, a, -1.0f, 1.0f));
    pk.h[6] = __float2bfloat16_rn(qclip(v1.z, a, -1.0f, 1.0f));
    pk.h[7] = __float2bfloat16_rn(qclip(v1.w, a, -1.0f, 1.0f));
    *reinterpret_cast<uint4*>(g_wq + i) = pk.u;
}

// ---------------------------------------------------------------------------
// Kernel 3: per-row absmax quantization of x -> bf16 integer codes.
// Warp-per-row; lane owns 64 consecutive floats (8 x 2 float4 streaming
// loads, 8 x uint4 stores); shfl-only max; no block barriers.
// ---------------------------------------------------------------------------
__global__ void __launch_bounds__(256)
k_quant(const float* __restrict__ x) {
    const int lane = threadIdx.x & 31;
    const int wrp  = threadIdx.x >> 5;
    const size_t row = (size_t)blockIdx.x * 8 + wrp;
    const float4* xr = reinterpret_cast<const float4*>(x + row * 2048) + lane * 2;

    float4 v[16];
    float m = 0.0f;
#pragma unroll
    for (int j = 0; j < 8; ++j) {
        v[2 * j]     = __ldcs(xr + 64 * j);       // 32B/lane, 1KB/warp contiguous
        v[2 * j + 1] = __ldcs(xr + 64 * j + 1);
        m = fmaxf(m, fmaxf(fmaxf(fabsf(v[2*j].x),   fabsf(v[2*j].y)),
                           fmaxf(fabsf(v[2*j].z),   fabsf(v[2*j].w))));
        m = fmaxf(m, fmaxf(fmaxf(fabsf(v[2*j+1].x), fabsf(v[2*j+1].y)),
                           fmaxf(fabsf(v[2*j+1].z), fabsf(v[2*j+1].w))));
    }
#pragma unroll
    for (int o = 16; o > 0; o >>= 1)
        m = fmaxf(m, __shfl_xor_sync(0xFFFFFFFFu, m, o));

    const float scale = __fdiv_rn(fmaxf(m, 1e-5f), 127.0f);
    if (lane == 0) g_scales[row] = scale;

    uint4* qr = reinterpret_cast<uint4*>(g_qx + row * 2048) + lane;
#pragma unroll
    for (int j = 0; j < 8; ++j) {
        union { uint4 u; __nv_bfloat16 h[8]; } pk;
        pk.h[0] = __float2bfloat16_rn(qclip(v[2*j].x,   scale, -128.0f, 127.0f));
        pk.h[1] = __float2bfloat16_rn(qclip(v[2*j].y,   scale, -128.0f, 127.0f));
        pk.h[2] = __float2bfloat16_rn(qclip(v[2*j].z,   scale, -128.0f, 127.0f));
        pk.h[3] = __float2bfloat16_rn(qclip(v[2*j].w,   scale, -128.0f, 127.0f));
        pk.h[4] = __float2bfloat16_rn(qclip(v[2*j+1].x, scale, -128.0f, 127.0f));
        pk.h[5] = __float2bfloat16_rn(qclip(v[2*j+1].y, scale, -128.0f, 127.0f));
        pk.h[6] = __float2bfloat16_rn(qclip(v[2*j+1].z, scale, -128.0f, 127.0f));
        pk.h[7] = __float2bfloat16_rn(qclip(v[2*j+1].w, scale, -128.0f, 127.0f));
        qr[32 * j] = pk.u;                        // 16B/lane, 512B/warp
    }
}

// ---------------------------------------------------------------------------
// Kernel 4: bf16 HMMA GEMM; BM=128 BN=128 BK=64; 4 warps x (64m x 64n);
//   3-stage cp.async pipeline; x3-unrolled mainloop; 2 CTAs/SM.  (R11, frozen)
// ---------------------------------------------------------------------------
static constexpr int BM = 128, BN = 128, BK = 64;       // BK in bf16 elements
static constexpr int STAGES = 3;
static constexpr int NITER = D_IN / BK;                 // 32
static constexpr int BKP = 144;                         // padded row bytes (128 data)
static constexpr int STAGE_BYTES = (BM + BN) * BKP;     // 36864
static constexpr int GEMM_SMEM = STAGES * STAGE_BYTES;  // 110592

__device__ __forceinline__ void mma_bf16(float* c, const uint32_t* a, const uint32_t* b) {
    asm volatile(
        "mma.sync.aligned.m16n8k16.row.col.f32.bf16.bf16.f32 "
        "{%0,%1,%2,%3}, {%4,%5,%6,%7}, {%8,%9}, {%0,%1,%2,%3};"
        : "+f"(c[0]), "+f"(c[1]), "+f"(c[2]), "+f"(c[3])
        : "r"(a[0]), "r"(a[1]), "r"(a[2]), "r"(a[3]), "r"(b[0]), "r"(b[1]));
}

__global__ void __launch_bounds__(128, 2)
gemm_kernel(const float* __restrict__ bias, float* __restrict__ out)
{
    extern __shared__ char smem[];
    const int tid = threadIdx.x;
    const int lane = tid & 31, wid = tid >> 5;
    const int warp_m = wid >> 1;          // 0..1 -> 64 rows each
    const int warp_n = wid & 1;           // 0..1 -> 64 cols each
    const int m0 = blockIdx.y * BM;
    const int n0 = blockIdx.x * BN;

    const __nv_bfloat16* gA = g_qx + (size_t)m0 * D_IN;
    const __nv_bfloat16* gB = g_wq + (size_t)n0 * D_IN;

    // full stage load: 2048 x 16B chunks (A: 1024, B: 1024); 16 per thread
    auto issue_stage = [&](uint32_t sOff, size_t kb) {
        char* aS = smem + sOff;
        char* bS = aS + BM * BKP;
#pragma unroll
        for (int h = 0; h < 16; ++h) {
            const int idx = tid + h * 128;          // [0,2048)
            if (idx < 1024) {
                const int row = idx >> 3, c = idx & 7;
                uint32_t dst = smem_u32(aS + row * BKP + c * 16);
                const char* src = (const char*)(gA + (size_t)row * D_IN) + kb + c * 16;
                asm volatile("cp.async.cg.shared.global [%0], [%1], 16;"
                             :: "r"(dst), "l"(src));
            } else {
                const int j = idx - 1024;
                const int row = j >> 3, c = j & 7;
                uint32_t dst = smem_u32(bS + row * BKP + c * 16);
                const char* src = (const char*)(gB + (size_t)row * D_IN) + kb + c * 16;
                asm volatile("cp.async.cg.shared.global [%0], [%1], 16;"
                             :: "r"(dst), "l"(src));
            }
        }
    };

    float acc[4][8][4];
#pragma unroll
    for (int i = 0; i < 4; ++i)
#pragma unroll
        for (int j = 0; j < 8; ++j)
#pragma unroll
            for (int k = 0; k < 4; ++k) acc[i][j][k] = 0.0f;

    // --- prologue: 2 stages in flight ---
    issue_stage(0 * STAGE_BYTES, 0 * (size_t)BK * 2);
    asm volatile("cp.async.commit_group;" ::: "memory");
    issue_stage(1 * STAGE_BYTES, 1 * (size_t)BK * 2);
    asm volatile("cp.async.commit_group;" ::: "memory");

    // ldmatrix per-lane base addresses
    const uint32_t smemb = smem_u32(smem);
    const uint32_t aLane = smemb
        + (uint32_t)(warp_m * 64 + (lane & 15)) * BKP + ((lane >> 4) << 4);
    const uint32_t bLane = smemb + BM * BKP
        + (uint32_t)(warp_n * 64 + ((lane >> 4) << 3) + (lane & 7)) * BKP
        + (((lane >> 3) & 1) << 4);

    // one iteration; S is a literal 0/1/2 -> all smem offsets constant-fold
    auto step = [&](const int S, const int it) {
        asm volatile("cp.async.wait_group 1;" ::: "memory");
        __syncthreads();

        const uint32_t cOff = (uint32_t)S * STAGE_BYTES;
        const int lS = (S + 2 >= STAGES) ? (S + 2 - STAGES) : (S + 2);
        const uint32_t lOff = (uint32_t)lS * STAGE_BYTES;
        const int lIt = it + STAGES - 1;

        // ---- ks = 0 first: restart tensor pipe immediately after barrier ----
        {
            uint32_t a[4][4], b[4][4];
#pragma unroll
            for (int mf = 0; mf < 4; ++mf)
                LDSM_X4(a[mf], aLane + cOff + (uint32_t)mf * (16 * BKP));
#pragma unroll
            for (int p = 0; p < 4; ++p)
                LDSM_X4(b[p], bLane + cOff + (uint32_t)p * (16 * BKP));
#pragma unroll
            for (int mf = 0; mf < 4; ++mf)
#pragma unroll
                for (int p = 0; p < 4; ++p) {
                    mma_bf16(acc[mf][p * 2 + 0], a[mf], &b[p][0]);
                    mma_bf16(acc[mf][p * 2 + 1], a[mf], &b[p][2]);
                }
        }

        // ---- deferred load burst (covered by ks0's HMMA drain) ----
        if (lIt < NITER)
            issue_stage(lOff, (size_t)lIt * BK * 2);
        asm volatile("cp.async.commit_group;" ::: "memory");  // uniform group count

        // ---- ks = 1..3 ----
#pragma unroll
        for (int ks = 1; ks < 4; ++ks) {
            const uint32_t kbc = (uint32_t)ks * 32;
            uint32_t a[4][4], b[4][4];
#pragma unroll
            for (int mf = 0; mf < 4; ++mf)
                LDSM_X4(a[mf], aLane + cOff + (uint32_t)mf * (16 * BKP) + kbc);
#pragma unroll
            for (int p = 0; p < 4; ++p)
                LDSM_X4(b[p], bLane + cOff + (uint32_t)p * (16 * BKP) + kbc);
#pragma unroll
            for (int mf = 0; mf < 4; ++mf)
#pragma unroll
                for (int p = 0; p < 4; ++p) {
                    mma_bf16(acc[mf][p * 2 + 0], a[mf], &b[p][0]);
                    mma_bf16(acc[mf][p * 2 + 1], a[mf], &b[p][2]);
                }
        }
    };

    // NITER = 32 = 3*10 + 2, stage literal = it % 3
    for (int base = 0; base < 30; base += 3) {
        step(0, base);
        step(1, base + 1);
        step(2, base + 2);
    }
    step(0, 30);
    step(1, 31);

    // --- epilogue: y = acc * (scale_row * alpha) + bias[col] ---
    const float alpha = g_alpha;
    const int colBase = n0 + warp_n * 64 + (lane & 3) * 2;
#pragma unroll
    for (int mf = 0; mf < 4; ++mf) {
        const int row0 = m0 + warp_m * 64 + mf * 16 + (lane >> 2);
        const float sc0 = g_scales[row0] * alpha;
        const float sc1 = g_scales[row0 + 8] * alpha;
        float* o0 = out + (size_t)row0 * D_OUT;
        float* o1 = o0 + (size_t)8 * D_OUT;
#pragma unroll
        for (int nf = 0; nf < 8; ++nf) {
            const int col = colBase + (nf >> 1) * 16 + (nf & 1) * 8;
            const float bx = bias[col], by = bias[col + 1];
            float2 v0, v1;
            v0.x = acc[mf][nf][0] * sc0 + bx;
            v0.y = acc[mf][nf][1] * sc0 + by;
            v1.x = acc[mf][nf][2] * sc1 + bx;
            v1.y = acc[mf][nf][3] * sc1 + by;
            *reinterpret_cast<float2*>(o0 + col) = v0;
            *reinterpret_cast<float2*>(o1 + col) = v1;
        }
    }
}

// ---------------------------------------------------------------------------
extern "C" void kernel_launch(void* const* d_in, const int* in_sizes, int n_in,
                              void* d_out, int out_size) {
    const float* x    = (const float*)d_in[0];   // [4, 8192, 2048]
    const float* w    = (const float*)d_in[1];   // [2048, 2048]
    const float* bias = (const float*)d_in[2];   // [2048]
    float* out = (float*)d_out;

    cudaFuncSetAttribute(gemm_kernel, cudaFuncAttributeMaxDynamicSharedMemorySize,
                         GEMM_SMEM);

    // exactly 4 launches: ncu capture slot (local idx 3) = gemm_kernel
    k_walpha<<<2048, 256>>>(w);
    k_ternarize<<<2048, 256>>>(w);
    k_quant<<<4096, 256>>>(x);
    gemm_kernel<<<dim3(D_OUT / BN, M_TOT / BM), 128, GEMM_SMEM>>>(bias, out);
}

// round 14
// speedup vs baseline: 1.0270x; 1.0270x over previous
#include <cuda_runtime.h>
#include <cuda_bf16.h>
#include <cstdint>
#include <cstddef>

// ============================================================================
// BitLinear on GB300, sm_103 baseline-PTX path:
//   bf16 HMMA GEMM on integer codes:  y = (absmax-int8(x)) @ ternary(W)^T + b
// codes exact in bf16; fp32 accum exact (|sum| < 2^24).
// R14: quant/ternarize reverted to R12 (R13 layout regressed: lane-contiguous
//      loads are warp-sparse per instruction). Single GEMM variable: deferred
//      cp.async burst moved after ks1 (more HMMA spacing from the barrier).
// ============================================================================

static constexpr int D_IN  = 2048;
static constexpr int D_OUT = 2048;
static constexpr int M_TOT = 32768;   // 4 * 8192

// scratch (allocation-free rule: device globals)
__device__ __nv_bfloat16 g_qx[(size_t)M_TOT * D_IN];   // 128 MB activation codes
__device__ __nv_bfloat16 g_wq[(size_t)D_OUT * D_IN];   // 8 MB ternary codes
__device__ float  g_scales[M_TOT];                     // per-row activation scale
__device__ float  g_partial[2048];                     // |W| partial sums
__device__ float  g_alpha;                             // ternary scale
__device__ unsigned int g_ctr;                         // last-block counter (self-resetting)

// ---------------------------------------------------------------------------
__device__ __forceinline__ float qclip(float v, float s, float lo, float hi) {
    return fminf(fmaxf(rintf(__fdiv_rn(v, s)), lo), hi);
}

__device__ __forceinline__ uint32_t smem_u32(const void* p) {
    uint32_t a;
    asm("{ .reg .u64 t; cvta.to.shared.u64 t, %1; cvt.u32.u64 %0, t; }"
        : "=r"(a) : "l"(p));
    return a;
}

#define LDSM_X4(r, addr) \
    asm volatile("ldmatrix.sync.aligned.m8n8.x4.shared.b16 {%0,%1,%2,%3}, [%4];" \
        : "=r"((r)[0]), "=r"((r)[1]), "=r"((r)[2]), "=r"((r)[3]) : "r"(addr))

// ---------------------------------------------------------------------------
// Kernel 1 (fused): per-block |W| partial sums + last-block final reduce.
// ---------------------------------------------------------------------------
__global__ void k_walpha(const float* __restrict__ w) {
    __shared__ float sh[256];
    __shared__ bool last;
    const int t = threadIdx.x;
    const float4* p = reinterpret_cast<const float4*>(w + (size_t)blockIdx.x * 2048);
    float s = 0.0f;
#pragma unroll
    for (int k = 0; k < 2; ++k) {
        float4 v = p[2 * t + k];
        s += fabsf(v.x) + fabsf(v.y) + fabsf(v.z) + fabsf(v.w);
    }
    sh[t] = s; __syncthreads();
    for (int o = 128; o > 0; o >>= 1) {
        if (t < o) sh[t] += sh[t + o];
        __syncthreads();
    }
    if (t == 0) {
        g_partial[blockIdx.x] = sh[0];
        __threadfence();
        last = (atomicAdd(&g_ctr, 1u) == 2047u);
    }
    __syncthreads();
    if (last) {
        float f = 0.0f;
        for (int i = t; i < 2048; i += 256) f += g_partial[i];
        sh[t] = f; __syncthreads();
        for (int o = 128; o > 0; o >>= 1) {
            if (t < o) sh[t] += sh[t + o];
            __syncthreads();
        }
        if (t == 0) {
            g_alpha = fmaxf(sh[0] * (1.0f / 4194304.0f), 1e-5f);
            g_ctr = 0u;          // reset for next graph replay
        }
    }
}

// Kernel 2: ternarize W -> bf16 codes {-1,0,1}   (R12 form)
__global__ void k_ternarize(const float* __restrict__ w) {
    const size_t i = ((size_t)blockIdx.x * 256 + threadIdx.x) * 4;
    const float a = g_alpha;
    float4 v = *reinterpret_cast<const float4*>(w + i);
    union { uint2 u; __nv_bfloat16 h[4]; } pk;
    pk.h[0] = __float2bfloat16_rn(qclip(v.x, a, -1.0f, 1.0f));
    pk.h[1] = __float2bfloat16_rn(qclip(v.y, a, -1.0f, 1.0f));
    pk.h[2] = __float2bfloat16_rn(qclip(v.z, a, -1.0f, 1.0f));
    pk.h[3] = __float2bfloat16_rn(qclip(v.w, a, -1.0f, 1.0f));
    *reinterpret_cast<uint2*>(g_wq + i) = pk.u;
}

// ---------------------------------------------------------------------------
// Kernel 3: per-row absmax quantization of x -> bf16 integer codes. (R12 form)
// Warp-per-row: 8 rows/block; lane-strided (warp-dense) loads & stores;
// shfl-only max; no block barriers.
// ---------------------------------------------------------------------------
__global__ void __launch_bounds__(256)
k_quant(const float* __restrict__ x) {
    const int lane = threadIdx.x & 31;
    const int wrp  = threadIdx.x >> 5;
    const size_t row = (size_t)blockIdx.x * 8 + wrp;
    const float4* xr = reinterpret_cast<const float4*>(x + row * 2048);

    float4 v[16];
    float m = 0.0f;
#pragma unroll
    for (int j = 0; j < 16; ++j) {
        v[j] = xr[lane + 32 * j];                 // coalesced, MLP=16
        m = fmaxf(m, fmaxf(fmaxf(fabsf(v[j].x), fabsf(v[j].y)),
                           fmaxf(fabsf(v[j].z), fabsf(v[j].w))));
    }
#pragma unroll
    for (int o = 16; o > 0; o >>= 1)
        m = fmaxf(m, __shfl_xor_sync(0xFFFFFFFFu, m, o));

    const float scale = __fdiv_rn(fmaxf(m, 1e-5f), 127.0f);
    if (lane == 0) g_scales[row] = scale;

    uint2* qr = reinterpret_cast<uint2*>(g_qx + row * 2048);
#pragma unroll
    for (int j = 0; j < 16; ++j) {
        union { uint2 u; __nv_bfloat16 h[4]; } pk;
        pk.h[0] = __float2bfloat16_rn(qclip(v[j].x, scale, -128.0f, 127.0f));
        pk.h[1] = __float2bfloat16_rn(qclip(v[j].y, scale, -128.0f, 127.0f));
        pk.h[2] = __float2bfloat16_rn(qclip(v[j].z, scale, -128.0f, 127.0f));
        pk.h[3] = __float2bfloat16_rn(qclip(v[j].w, scale, -128.0f, 127.0f));
        qr[lane + 32 * j] = pk.u;                 // coalesced 256B/warp
    }
}

// ---------------------------------------------------------------------------
// Kernel 4: bf16 HMMA GEMM; BM=128 BN=128 BK=64; 4 warps x (64m x 64n);
//   3-stage cp.async pipeline; x3-unrolled mainloop; 2 CTAs/SM.
//   R14 delta: deferred load burst after ks1 (was after ks0).
// ---------------------------------------------------------------------------
static constexpr int BM = 128, BN = 128, BK = 64;       // BK in bf16 elements
static constexpr int STAGES = 3;
static constexpr int NITER = D_IN / BK;                 // 32
static constexpr int BKP = 144;                         // padded row bytes (128 data)
static constexpr int STAGE_BYTES = (BM + BN) * BKP;     // 36864
static constexpr int GEMM_SMEM = STAGES * STAGE_BYTES;  // 110592

__device__ __forceinline__ void mma_bf16(float* c, const uint32_t* a, const uint32_t* b) {
    asm volatile(
        "mma.sync.aligned.m16n8k16.row.col.f32.bf16.bf16.f32 "
        "{%0,%1,%2,%3}, {%4,%5,%6,%7}, {%8,%9}, {%0,%1,%2,%3};"
        : "+f"(c[0]), "+f"(c[1]), "+f"(c[2]), "+f"(c[3])
        : "r"(a[0]), "r"(a[1]), "r"(a[2]), "r"(a[3]), "r"(b[0]), "r"(b[1]));
}

__global__ void __launch_bounds__(128, 2)
gemm_kernel(const float* __restrict__ bias, float* __restrict__ out)
{
    extern __shared__ char smem[];
    const int tid = threadIdx.x;
    const int lane = tid & 31, wid = tid >> 5;
    const int warp_m = wid >> 1;          // 0..1 -> 64 rows each
    const int warp_n = wid & 1;           // 0..1 -> 64 cols each
    const int m0 = blockIdx.y * BM;
    const int n0 = blockIdx.x * BN;

    const __nv_bfloat16* gA = g_qx + (size_t)m0 * D_IN;
    const __nv_bfloat16* gB = g_wq + (size_t)n0 * D_IN;

    // full stage load: 2048 x 16B chunks (A: 1024, B: 1024); 16 per thread
    auto issue_stage = [&](uint32_t sOff, size_t kb) {
        char* aS = smem + sOff;
        char* bS = aS + BM * BKP;
#pragma unroll
        for (int h = 0; h < 16; ++h) {
            const int idx = tid + h * 128;          // [0,2048)
            if (idx < 1024) {
                const int row = idx >> 3, c = idx & 7;
                uint32_t dst = smem_u32(aS + row * BKP + c * 16);
                const char* src = (const char*)(gA + (size_t)row * D_IN) + kb + c * 16;
                asm volatile("cp.async.cg.shared.global [%0], [%1], 16;"
                             :: "r"(dst), "l"(src));
            } else {
                const int j = idx - 1024;
                const int row = j >> 3, c = j & 7;
                uint32_t dst = smem_u32(bS + row * BKP + c * 16);
                const char* src = (const char*)(gB + (size_t)row * D_IN) + kb + c * 16;
                asm volatile("cp.async.cg.shared.global [%0], [%1], 16;"
                             :: "r"(dst), "l"(src));
            }
        }
    };

    float acc[4][8][4];
#pragma unroll
    for (int i = 0; i < 4; ++i)
#pragma unroll
        for (int j = 0; j < 8; ++j)
#pragma unroll
            for (int k = 0; k < 4; ++k) acc[i][j][k] = 0.0f;

    // --- prologue: 2 stages in flight ---
    issue_stage(0 * STAGE_BYTES, 0 * (size_t)BK * 2);
    asm volatile("cp.async.commit_group;" ::: "memory");
    issue_stage(1 * STAGE_BYTES, 1 * (size_t)BK * 2);
    asm volatile("cp.async.commit_group;" ::: "memory");

    // ldmatrix per-lane base addresses
    const uint32_t smemb = smem_u32(smem);
    const uint32_t aLane = smemb
        + (uint32_t)(warp_m * 64 + (lane & 15)) * BKP + ((lane >> 4) << 4);
    const uint32_t bLane = smemb + BM * BKP
        + (uint32_t)(warp_n * 64 + ((lane >> 4) << 3) + (lane & 7)) * BKP
        + (((lane >> 3) & 1) << 4);

    // one ks group: 8 LDSM + 32 HMMA at compute offset cOff
    auto ks_group = [&](uint32_t cOff, uint32_t kbc) {
        uint32_t a[4][4], b[4][4];
#pragma unroll
        for (int mf = 0; mf < 4; ++mf)
            LDSM_X4(a[mf], aLane + cOff + (uint32_t)mf * (16 * BKP) + kbc);
#pragma unroll
        for (int p = 0; p < 4; ++p)
            LDSM_X4(b[p], bLane + cOff + (uint32_t)p * (16 * BKP) + kbc);
#pragma unroll
        for (int mf = 0; mf < 4; ++mf)
#pragma unroll
            for (int p = 0; p < 4; ++p) {
                mma_bf16(acc[mf][p * 2 + 0], a[mf], &b[p][0]);
                mma_bf16(acc[mf][p * 2 + 1], a[mf], &b[p][2]);
            }
    };

    // one iteration; S is a literal 0/1/2 -> all smem offsets constant-fold
    auto step = [&](const int S, const int it) {
        asm volatile("cp.async.wait_group 1;" ::: "memory");
        __syncthreads();

        const uint32_t cOff = (uint32_t)S * STAGE_BYTES;
        const int lS = (S + 2 >= STAGES) ? (S + 2 - STAGES) : (S + 2);
        const uint32_t lOff = (uint32_t)lS * STAGE_BYTES;
        const int lIt = it + STAGES - 1;

        // ks = 0,1: restart tensor pipe immediately after barrier
        ks_group(cOff, 0);
        ks_group(cOff, 32);

        // deferred load burst (covered by ks0+ks1 HMMA drain)
        if (lIt < NITER)
            issue_stage(lOff, (size_t)lIt * BK * 2);
        asm volatile("cp.async.commit_group;" ::: "memory");  // uniform group count

        // ks = 2,3
        ks_group(cOff, 64);
        ks_group(cOff, 96);
    };

    // NITER = 32 = 3*10 + 2, stage literal = it % 3
    for (int base = 0; base < 30; base += 3) {
        step(0, base);
        step(1, base + 1);
        step(2, base + 2);
    }
    step(0, 30);
    step(1, 31);

    // --- epilogue: y = acc * (scale_row * alpha) + bias[col] ---
    const float alpha = g_alpha;
    const int colBase = n0 + warp_n * 64 + (lane & 3) * 2;
#pragma unroll
    for (int mf = 0; mf < 4; ++mf) {
        const int row0 = m0 + warp_m * 64 + mf * 16 + (lane >> 2);
        const float sc0 = g_scales[row0] * alpha;
        const float sc1 = g_scales[row0 + 8] * alpha;
        float* o0 = out + (size_t)row0 * D_OUT;
        float* o1 = o0 + (size_t)8 * D_OUT;
#pragma unroll
        for (int nf = 0; nf < 8; ++nf) {
            const int col = colBase + (nf >> 1) * 16 + (nf & 1) * 8;
            const float bx = bias[col], by = bias[col + 1];
            float2 v0, v1;
            v0.x = acc[mf][nf][0] * sc0 + bx;
            v0.y = acc[mf][nf][1] * sc0 + by;
            v1.x = acc[mf][nf][2] * sc1 + bx;
            v1.y = acc[mf][nf][3] * sc1 + by;
            *reinterpret_cast<float2*>(o0 + col) = v0;
            *reinterpret_cast<float2*>(o1 + col) = v1;
        }
    }
}

// ---------------------------------------------------------------------------
extern "C" void kernel_launch(void* const* d_in, const int* in_sizes, int n_in,
                              void* d_out, int out_size) {
    const float* x    = (const float*)d_in[0];   // [4, 8192, 2048]
    const float* w    = (const float*)d_in[1];   // [2048, 2048]
    const float* bias = (const float*)d_in[2];   // [2048]
    float* out = (float*)d_out;

    cudaFuncSetAttribute(gemm_kernel, cudaFuncAttributeMaxDynamicSharedMemorySize,
                         GEMM_SMEM);

    // exactly 4 launches: ncu capture slot (local idx 3) = gemm_kernel
    k_walpha<<<2048, 256>>>(w);
    k_ternarize<<<4096, 256>>>(w);
    k_quant<<<4096, 256>>>(x);
    gemm_kernel<<<dim3(D_OUT / BN, M_TOT / BM), 128, GEMM_SMEM>>>(bias, out);
}

// round 15
// speedup vs baseline: 1.0376x; 1.0103x over previous
#include <cuda_runtime.h>
#include <cuda_bf16.h>
#include <cstdint>
#include <cstddef>

// ============================================================================
// BitLinear on GB300, sm_103 baseline-PTX path:
//   bf16 HMMA GEMM on integer codes:  y = (absmax-int8(x)) @ ternary(W)^T + b
// codes exact in bf16; fp32 accum exact (|sum| < 2^24).
// R15: single variable vs R14 — deferred cp.async burst moved after ks2
//      (gradient: ks0->ks1 placement gained 15us; one more step).
// ============================================================================

static constexpr int D_IN  = 2048;
static constexpr int D_OUT = 2048;
static constexpr int M_TOT = 32768;   // 4 * 8192

// scratch (allocation-free rule: device globals)
__device__ __nv_bfloat16 g_qx[(size_t)M_TOT * D_IN];   // 128 MB activation codes
__device__ __nv_bfloat16 g_wq[(size_t)D_OUT * D_IN];   // 8 MB ternary codes
__device__ float  g_scales[M_TOT];                     // per-row activation scale
__device__ float  g_partial[2048];                     // |W| partial sums
__device__ float  g_alpha;                             // ternary scale
__device__ unsigned int g_ctr;                         // last-block counter (self-resetting)

// ---------------------------------------------------------------------------
__device__ __forceinline__ float qclip(float v, float s, float lo, float hi) {
    return fminf(fmaxf(rintf(__fdiv_rn(v, s)), lo), hi);
}

__device__ __forceinline__ uint32_t smem_u32(const void* p) {
    uint32_t a;
    asm("{ .reg .u64 t; cvta.to.shared.u64 t, %1; cvt.u32.u64 %0, t; }"
        : "=r"(a) : "l"(p));
    return a;
}

#define LDSM_X4(r, addr) \
    asm volatile("ldmatrix.sync.aligned.m8n8.x4.shared.b16 {%0,%1,%2,%3}, [%4];" \
        : "=r"((r)[0]), "=r"((r)[1]), "=r"((r)[2]), "=r"((r)[3]) : "r"(addr))

// ---------------------------------------------------------------------------
// Kernel 1 (fused): per-block |W| partial sums + last-block final reduce.
// ---------------------------------------------------------------------------
__global__ void k_walpha(const float* __restrict__ w) {
    __shared__ float sh[256];
    __shared__ bool last;
    const int t = threadIdx.x;
    const float4* p = reinterpret_cast<const float4*>(w + (size_t)blockIdx.x * 2048);
    float s = 0.0f;
#pragma unroll
    for (int k = 0; k < 2; ++k) {
        float4 v = p[2 * t + k];
        s += fabsf(v.x) + fabsf(v.y) + fabsf(v.z) + fabsf(v.w);
    }
    sh[t] = s; __syncthreads();
    for (int o = 128; o > 0; o >>= 1) {
        if (t < o) sh[t] += sh[t + o];
        __syncthreads();
    }
    if (t == 0) {
        g_partial[blockIdx.x] = sh[0];
        __threadfence();
        last = (atomicAdd(&g_ctr, 1u) == 2047u);
    }
    __syncthreads();
    if (last) {
        float f = 0.0f;
        for (int i = t; i < 2048; i += 256) f += g_partial[i];
        sh[t] = f; __syncthreads();
        for (int o = 128; o > 0; o >>= 1) {
            if (t < o) sh[t] += sh[t + o];
            __syncthreads();
        }
        if (t == 0) {
            g_alpha = fmaxf(sh[0] * (1.0f / 4194304.0f), 1e-5f);
            g_ctr = 0u;          // reset for next graph replay
        }
    }
}

// Kernel 2: ternarize W -> bf16 codes {-1,0,1}
__global__ void k_ternarize(const float* __restrict__ w) {
    const size_t i = ((size_t)blockIdx.x * 256 + threadIdx.x) * 4;
    const float a = g_alpha;
    float4 v = *reinterpret_cast<const float4*>(w + i);
    union { uint2 u; __nv_bfloat16 h[4]; } pk;
    pk.h[0] = __float2bfloat16_rn(qclip(v.x, a, -1.0f, 1.0f));
    pk.h[1] = __float2bfloat16_rn(qclip(v.y, a, -1.0f, 1.0f));
    pk.h[2] = __float2bfloat16_rn(qclip(v.z, a, -1.0f, 1.0f));
    pk.h[3] = __float2bfloat16_rn(qclip(v.w, a, -1.0f, 1.0f));
    *reinterpret_cast<uint2*>(g_wq + i) = pk.u;
}

// ---------------------------------------------------------------------------
// Kernel 3: per-row absmax quantization of x -> bf16 integer codes.
// Warp-per-row: 8 rows/block; lane-strided (warp-dense) loads & stores;
// shfl-only max; no block barriers.
// ---------------------------------------------------------------------------
__global__ void __launch_bounds__(256)
k_quant(const float* __restrict__ x) {
    const int lane = threadIdx.x & 31;
    const int wrp  = threadIdx.x >> 5;
    const size_t row = (size_t)blockIdx.x * 8 + wrp;
    const float4* xr = reinterpret_cast<const float4*>(x + row * 2048);

    float4 v[16];
    float m = 0.0f;
#pragma unroll
    for (int j = 0; j < 16; ++j) {
        v[j] = xr[lane + 32 * j];                 // coalesced, MLP=16
        m = fmaxf(m, fmaxf(fmaxf(fabsf(v[j].x), fabsf(v[j].y)),
                           fmaxf(fabsf(v[j].z), fabsf(v[j].w))));
    }
#pragma unroll
    for (int o = 16; o > 0; o >>= 1)
        m = fmaxf(m, __shfl_xor_sync(0xFFFFFFFFu, m, o));

    const float scale = __fdiv_rn(fmaxf(m, 1e-5f), 127.0f);
    if (lane == 0) g_scales[row] = scale;

    uint2* qr = reinterpret_cast<uint2*>(g_qx + row * 2048);
#pragma unroll
    for (int j = 0; j < 16; ++j) {
        union { uint2 u; __nv_bfloat16 h[4]; } pk;
        pk.h[0] = __float2bfloat16_rn(qclip(v[j].x, scale, -128.0f, 127.0f));
        pk.h[1] = __float2bfloat16_rn(qclip(v[j].y, scale, -128.0f, 127.0f));
        pk.h[2] = __float2bfloat16_rn(qclip(v[j].z, scale, -128.0f, 127.0f));
        pk.h[3] = __float2bfloat16_rn(qclip(v[j].w, scale, -128.0f, 127.0f));
        qr[lane + 32 * j] = pk.u;                 // coalesced 256B/warp
    }
}

// ---------------------------------------------------------------------------
// Kernel 4: bf16 HMMA GEMM; BM=128 BN=128 BK=64; 4 warps x (64m x 64n);
//   3-stage cp.async pipeline; x3-unrolled mainloop; 2 CTAs/SM.
//   R15 delta: deferred load burst after ks2 (was after ks1).
// ---------------------------------------------------------------------------
static constexpr int BM = 128, BN = 128, BK = 64;       // BK in bf16 elements
static constexpr int STAGES = 3;
static constexpr int NITER = D_IN / BK;                 // 32
static constexpr int BKP = 144;                         // padded row bytes (128 data)
static constexpr int STAGE_BYTES = (BM + BN) * BKP;     // 36864
static constexpr int GEMM_SMEM = STAGES * STAGE_BYTES;  // 110592

__device__ __forceinline__ void mma_bf16(float* c, const uint32_t* a, const uint32_t* b) {
    asm volatile(
        "mma.sync.aligned.m16n8k16.row.col.f32.bf16.bf16.f32 "
        "{%0,%1,%2,%3}, {%4,%5,%6,%7}, {%8,%9}, {%0,%1,%2,%3};"
        : "+f"(c[0]), "+f"(c[1]), "+f"(c[2]), "+f"(c[3])
        : "r"(a[0]), "r"(a[1]), "r"(a[2]), "r"(a[3]), "r"(b[0]), "r"(b[1]));
}

__global__ void __launch_bounds__(128, 2)
gemm_kernel(const float* __restrict__ bias, float* __restrict__ out)
{
    extern __shared__ char smem[];
    const int tid = threadIdx.x;
    const int lane = tid & 31, wid = tid >> 5;
    const int warp_m = wid >> 1;          // 0..1 -> 64 rows each
    const int warp_n = wid & 1;           // 0..1 -> 64 cols each
    const int m0 = blockIdx.y * BM;
    const int n0 = blockIdx.x * BN;

    const __nv_bfloat16* gA = g_qx + (size_t)m0 * D_IN;
    const __nv_bfloat16* gB = g_wq + (size_t)n0 * D_IN;

    // full stage load: 2048 x 16B chunks (A: 1024, B: 1024); 16 per thread
    auto issue_stage = [&](uint32_t sOff, size_t kb) {
        char* aS = smem + sOff;
        char* bS = aS + BM * BKP;
#pragma unroll
        for (int h = 0; h < 16; ++h) {
            const int idx = tid + h * 128;          // [0,2048)
            if (idx < 1024) {
                const int row = idx >> 3, c = idx & 7;
                uint32_t dst = smem_u32(aS + row * BKP + c * 16);
                const char* src = (const char*)(gA + (size_t)row * D_IN) + kb + c * 16;
                asm volatile("cp.async.cg.shared.global [%0], [%1], 16;"
                             :: "r"(dst), "l"(src));
            } else {
                const int j = idx - 1024;
                const int row = j >> 3, c = j & 7;
                uint32_t dst = smem_u32(bS + row * BKP + c * 16);
                const char* src = (const char*)(gB + (size_t)row * D_IN) + kb + c * 16;
                asm volatile("cp.async.cg.shared.global [%0], [%1], 16;"
                             :: "r"(dst), "l"(src));
            }
        }
    };

    float acc[4][8][4];
#pragma unroll
    for (int i = 0; i < 4; ++i)
#pragma unroll
        for (int j = 0; j < 8; ++j)
#pragma unroll
            for (int k = 0; k < 4; ++k) acc[i][j][k] = 0.0f;

    // --- prologue: 2 stages in flight ---
    issue_stage(0 * STAGE_BYTES, 0 * (size_t)BK * 2);
    asm volatile("cp.async.commit_group;" ::: "memory");
    issue_stage(1 * STAGE_BYTES, 1 * (size_t)BK * 2);
    asm volatile("cp.async.commit_group;" ::: "memory");

    // ldmatrix per-lane base addresses
    const uint32_t smemb = smem_u32(smem);
    const uint32_t aLane = smemb
        + (uint32_t)(warp_m * 64 + (lane & 15)) * BKP + ((lane >> 4) << 4);
    const uint32_t bLane = smemb + BM * BKP
        + (uint32_t)(warp_n * 64 + ((lane >> 4) << 3) + (lane & 7)) * BKP
        + (((lane >> 3) & 1) << 4);

    // one ks group: 8 LDSM + 32 HMMA at compute offset cOff
    auto ks_group = [&](uint32_t cOff, uint32_t kbc) {
        uint32_t a[4][4], b[4][4];
#pragma unroll
        for (int mf = 0; mf < 4; ++mf)
            LDSM_X4(a[mf], aLane + cOff + (uint32_t)mf * (16 * BKP) + kbc);
#pragma unroll
        for (int p = 0; p < 4; ++p)
            LDSM_X4(b[p], bLane + cOff + (uint32_t)p * (16 * BKP) + kbc);
#pragma unroll
        for (int mf = 0; mf < 4; ++mf)
#pragma unroll
            for (int p = 0; p < 4; ++p) {
                mma_bf16(acc[mf][p * 2 + 0], a[mf], &b[p][0]);
                mma_bf16(acc[mf][p * 2 + 1], a[mf], &b[p][2]);
            }
    };

    // one iteration; S is a literal 0/1/2 -> all smem offsets constant-fold
    auto step = [&](const int S, const int it) {
        asm volatile("cp.async.wait_group 1;" ::: "memory");
        __syncthreads();

        const uint32_t cOff = (uint32_t)S * STAGE_BYTES;
        const int lS = (S + 2 >= STAGES) ? (S + 2 - STAGES) : (S + 2);
        const uint32_t lOff = (uint32_t)lS * STAGE_BYTES;
        const int lIt = it + STAGES - 1;

        // ks = 0..2: restart tensor pipe immediately after barrier
        ks_group(cOff, 0);
        ks_group(cOff, 32);
        ks_group(cOff, 64);

        // deferred load burst (mid-iteration, max distance from both barriers)
        if (lIt < NITER)
            issue_stage(lOff, (size_t)lIt * BK * 2);
        asm volatile("cp.async.commit_group;" ::: "memory");  // uniform group count

        // ks = 3
        ks_group(cOff, 96);
    };

    // NITER = 32 = 3*10 + 2, stage literal = it % 3
    for (int base = 0; base < 30; base += 3) {
        step(0, base);
        step(1, base + 1);
        step(2, base + 2);
    }
    step(0, 30);
    step(1, 31);

    // --- epilogue: y = acc * (scale_row * alpha) + bias[col] ---
    const float alpha = g_alpha;
    const int colBase = n0 + warp_n * 64 + (lane & 3) * 2;
#pragma unroll
    for (int mf = 0; mf < 4; ++mf) {
        const int row0 = m0 + warp_m * 64 + mf * 16 + (lane >> 2);
        const float sc0 = g_scales[row0] * alpha;
        const float sc1 = g_scales[row0 + 8] * alpha;
        float* o0 = out + (size_t)row0 * D_OUT;
        float* o1 = o0 + (size_t)8 * D_OUT;
#pragma unroll
        for (int nf = 0; nf < 8; ++nf) {
            const int col = colBase + (nf >> 1) * 16 + (nf & 1) * 8;
            const float bx = bias[col], by = bias[col + 1];
            float2 v0, v1;
            v0.x = acc[mf][nf][0] * sc0 + bx;
            v0.y = acc[mf][nf][1] * sc0 + by;
            v1.x = acc[mf][nf][2] * sc1 + bx;
            v1.y = acc[mf][nf][3] * sc1 + by;
            *reinterpret_cast<float2*>(o0 + col) = v0;
            *reinterpret_cast<float2*>(o1 + col) = v1;
        }
    }
}

// ---------------------------------------------------------------------------
extern "C" void kernel_launch(void* const* d_in, const int* in_sizes, int n_in,
                              void* d_out, int out_size) {
    const float* x    = (const float*)d_in[0];   // [4, 8192, 2048]
    const float* w    = (const float*)d_in[1];   // [2048, 2048]
    const float* bias = (const float*)d_in[2];   // [2048]
    float* out = (float*)d_out;

    cudaFuncSetAttribute(gemm_kernel, cudaFuncAttributeMaxDynamicSharedMemorySize,
                         GEMM_SMEM);

    // exactly 4 launches: ncu capture slot (local idx 3) = gemm_kernel
    k_walpha<<<2048, 256>>>(w);
    k_ternarize<<<4096, 256>>>(w);
    k_quant<<<4096, 256>>>(x);
    gemm_kernel<<<dim3(D_OUT / BN, M_TOT / BM), 128, GEMM_SMEM>>>(bias, out);
}